// round 15
// baseline (speedup 1.0000x reference)
#include <cuda_runtime.h>
#include <cuda_fp16.h>
#include <math.h>
#include <stdint.h>

// ---------------- problem constants ----------------
#define D_LLM 4096
#define D_FF  11008
#define NB    8
#define SEQ   256
#define SP    128
#define NH    32
#define HD    128
#define MROWS (NB*SEQ)          // 2048
#define MTV   (NB*128)          // 1024 text+vision rows
#define EPSR  1e-5f

// fp16 weight scratch layout (element offsets match fp32 source shapes)
#define WSZ_ATT  (D_LLM*D_LLM)
#define WSZ_FF   (D_LLM*D_FF)
#define L_WQ   ((size_t)0)
#define L_WK   ((size_t)1*WSZ_ATT)
#define L_WV   ((size_t)2*WSZ_ATT)
#define L_WO   ((size_t)3*WSZ_ATT)
#define L_WG   ((size_t)4*WSZ_ATT)
#define L_WU   ((size_t)4*WSZ_ATT + WSZ_FF)
#define L_WD   ((size_t)4*WSZ_ATT + 2*(size_t)WSZ_FF)
#define LAYER_STRIDE ((size_t)4*WSZ_ATT + 3*(size_t)WSZ_FF)

// ---------------- scratch (device globals; no allocation) ----------------
__device__ float  g_h   [MROWS*D_LLM];
__device__ float  g_x   [MROWS*D_LLM];
__device__ __half g_xh  [MROWS*D_LLM];
__device__ float  g_q   [MROWS*D_LLM];
__device__ float  g_k   [MROWS*D_LLM];
__device__ float  g_v   [MROWS*D_LLM];
__device__ __half g_oh  [MROWS*D_LLM];
__device__ float  g_att [NB*NH*SEQ*SEQ];
__device__ float  g_gate[MROWS*D_FF];
__device__ float  g_up  [MROWS*D_FF];
__device__ __half g_gh  [MROWS*D_FF];
__device__ __half g_tvh [MTV*768];
__device__ float  g_pool[NB*D_LLM];
__device__ float  g_y1  [NB*768];
__device__ __half g_wh  [2*LAYER_STRIDE];     // fp16, k-pair-interleaved weights
__device__ __half g_inWh[768*D_LLM];

// ---------------- helpers ----------------
__device__ __forceinline__ void cp_async16_s(uint32_t saddr, const void* gmem_src){
    asm volatile("cp.async.cg.shared.global [%0], [%1], 16;\n" :: "r"(saddr), "l"(gmem_src));
}
__device__ __forceinline__ void cp_commit(){
    asm volatile("cp.async.commit_group;\n" ::: "memory");
}
template<int N>
__device__ __forceinline__ void cp_wait(){
    asm volatile("cp.async.wait_group %0;\n" :: "n"(N) : "memory");
}

__device__ __forceinline__ void mma_f16(float* d, uint32_t a0, uint32_t a1, uint32_t a2, uint32_t a3,
                                        uint32_t b0, uint32_t b1){
    asm volatile(
        "mma.sync.aligned.m16n8k16.row.col.f32.f16.f16.f32 "
        "{%0,%1,%2,%3}, {%4,%5,%6,%7}, {%8,%9}, {%0,%1,%2,%3};"
        : "+f"(d[0]), "+f"(d[1]), "+f"(d[2]), "+f"(d[3])
        : "r"(a0), "r"(a1), "r"(a2), "r"(a3), "r"(b0), "r"(b1));
}

__device__ __forceinline__ void ldmatrix_x4(uint32_t& r0, uint32_t& r1, uint32_t& r2, uint32_t& r3,
                                            uint32_t saddr){
    asm volatile("ldmatrix.sync.aligned.m8n8.x4.shared.b16 {%0,%1,%2,%3}, [%4];"
        : "=r"(r0), "=r"(r1), "=r"(r2), "=r"(r3) : "r"(saddr));
}

// ---------------- block reductions ----------------
__device__ __forceinline__ float blockReduceSum(float v){
    __shared__ float sh[33];
    int lane = threadIdx.x & 31, w = threadIdx.x >> 5;
    #pragma unroll
    for (int o=16;o>0;o>>=1) v += __shfl_down_sync(0xffffffffu, v, o);
    if (lane==0) sh[w]=v;
    __syncthreads();
    if (threadIdx.x==0){
        float s = 0.f;
        int nw = (blockDim.x+31)>>5;
        for (int i=0;i<nw;i++) s += sh[i];
        sh[32]=s;
    }
    __syncthreads();
    float r = sh[32];
    __syncthreads();
    return r;
}
__device__ __forceinline__ float blockReduceMax(float v){
    __shared__ float sh[33];
    int lane = threadIdx.x & 31, w = threadIdx.x >> 5;
    #pragma unroll
    for (int o=16;o>0;o>>=1) v = fmaxf(v, __shfl_down_sync(0xffffffffu, v, o));
    if (lane==0) sh[w]=v;
    __syncthreads();
    if (threadIdx.x==0){
        float s = -3.0e38f;
        int nw = (blockDim.x+31)>>5;
        for (int i=0;i<nw;i++) s = fmaxf(s, sh[i]);
        sh[32]=s;
    }
    __syncthreads();
    float r = sh[32];
    __syncthreads();
    return r;
}

// ---------------- weight fp32 -> fp16 with k-pair interleave (vectorized) ----------------
__global__ void cvt_w(const float* __restrict__ in, __half* __restrict__ out, int N4, int half_rows)
{
    int idx = blockIdx.x*256 + threadIdx.x;
    if (idx >= half_rows*N4) return;
    int k2 = idx / N4, n4 = idx - k2*N4;
    float4 v0 = ((const float4*)in)[(size_t)(2*k2  )*N4 + n4];
    float4 v1 = ((const float4*)in)[(size_t)(2*k2+1)*N4 + n4];
    __half2 h0 = __floats2half2_rn(v0.x, v1.x);
    __half2 h1 = __floats2half2_rn(v0.y, v1.y);
    __half2 h2 = __floats2half2_rn(v0.z, v1.z);
    __half2 h3 = __floats2half2_rn(v0.w, v1.w);
    uint4 pack;
    pack.x = *(uint32_t*)&h0; pack.y = *(uint32_t*)&h1;
    pack.z = *(uint32_t*)&h2; pack.w = *(uint32_t*)&h3;
    ((uint4*)out)[(size_t)k2*N4 + n4] = pack;
}

// ---------------- FP16 mma.sync GEMM, 256x128 tile, 8 warps (64x64 warp tile) ----------------
//   C[M,N](f32) = A[M,K](f16) @ B[K,N](f16, k-pair interleaved)
// EPI: 0 plain, 1 +bias & row-remap (in_proj), 2 += resid
// Requires: M%256==0, N%128==0, K%32==0, K/32 >= 3.
#define TCS 3
#define BM 256
#define BN 128
#define CK 32
#define A_B32 20                 // b32 per A smem row (16 data + 4 pad)
#define A_STG (BM*A_B32)         // 5120 b32
#define B_B32 136                // b32 per B smem row (128 data + 8 pad)
#define B_STG ((CK/2)*B_B32)     // 2176 b32
#define TC_SMEM (TCS*(A_STG+B_STG)*4)   // 87552 B

template<int EPI>
__global__ void __launch_bounds__(256, 1)
gemm_mma(const __half* __restrict__ A, const __half* __restrict__ B,
         float* __restrict__ C, const float* __restrict__ bias,
         const float* __restrict__ resid, int M, int N, int K)
{
    extern __shared__ uint32_t sm32[];
    const uint32_t sb = (uint32_t)__cvta_generic_to_shared(sm32);

    const int tid = threadIdx.x;
    const int wid = tid >> 5, lane = tid & 31;
    const int g   = lane >> 2, tig = lane & 3;
    const int lrow = lane & 15, lsel = lane >> 4;     // ldmatrix addressing
    const int wm  = wid >> 1;                // 0..3 (64 rows each)
    const int wn  = wid & 1;                 // 0..1 (64 cols each)
    const int m0  = blockIdx.x * BM;
    const int n0  = blockIdx.y * BN;
    const int KT  = K >> 5;
    const __half2* B2p = (const __half2*)B;

    float acc[4][8][4];                      // [mf][nf][reg]
    #pragma unroll
    for (int i=0;i<4;i++)
        #pragma unroll
        for (int j=0;j<8;j++)
            #pragma unroll
            for (int t=0;t<4;t++) acc[i][j][t]=0.f;

    auto load_chunk = [&](int st, int kc){
        const int k0 = kc << 5;              // in halves
        const uint32_t ab = sb + (uint32_t)(st*A_STG*4);
        const uint32_t bb = sb + (uint32_t)((TCS*A_STG + st*B_STG)*4);
        #pragma unroll
        for (int it=0; it<4; it++){                      // A: 256 rows x 4 x 16B (8 halves)
            int qi = tid + it*256;
            int r  = qi >> 2, c4 = qi & 3;
            cp_async16_s(ab + (uint32_t)(r*(A_B32*4) + c4*16),
                         A + (size_t)(m0+r)*K + k0 + c4*8);
        }
        #pragma unroll
        for (int it=0; it<2; it++){                      // B: 16 rows x 32 x 16B (4 half2)
            int qi = tid + it*256;
            int r2 = qi >> 5, cb = qi & 31;
            cp_async16_s(bb + (uint32_t)(r2*(B_B32*4) + cb*16),
                         B2p + (size_t)((k0>>1)+r2)*N + n0 + cb*4);
        }
    };

    auto compute = [&](int st){
        const uint32_t abase = sb + (uint32_t)(st*A_STG*4);
        const uint32_t* Bs = sm32 + TCS*A_STG + st*B_STG;
        #pragma unroll
        for (int ks2=0; ks2<CK/2; ks2+=8){   // two k-16 steps
            uint32_t bfr[8][2];
            #pragma unroll
            for (int nf=0; nf<8; nf++){
                int col = wn*64 + nf*8 + g;
                bfr[nf][0] = Bs[(ks2+tig  )*B_B32 + col];
                bfr[nf][1] = Bs[(ks2+tig+4)*B_B32 + col];
            }
            #pragma unroll
            for (int mf=0; mf<4; mf++){
                int row = wm*64 + mf*16;
                uint32_t a0,a1,a2,a3;
                uint32_t addr = abase + (uint32_t)(((row + lrow)*A_B32 + ks2 + lsel*4)*4);
                ldmatrix_x4(a0, a1, a2, a3, addr);
                #pragma unroll
                for (int nf=0; nf<8; nf++)
                    mma_f16(acc[mf][nf], a0, a1, a2, a3, bfr[nf][0], bfr[nf][1]);
            }
        }
    };

    load_chunk(0, 0); cp_commit();
    load_chunk(1, 1); cp_commit();

    int st = 0;
    for (int kt=0; kt<KT; kt++){
        cp_wait<1>();
        __syncthreads();
        compute(st);
        int nc = kt + 2;
        if (nc < KT){
            int ns = st + 2; if (ns >= TCS) ns -= TCS;
            load_chunk(ns, nc);
        }
        cp_commit();
        st = (st+1 == TCS) ? 0 : st+1;
    }

    // epilogue
    #pragma unroll
    for (int mf=0; mf<4; mf++){
        int mrow = m0 + wm*64 + mf*16 + g;               // logical input row
        int r0 = (EPI==1) ? (((mrow>>7)<<8) + 128 + (mrow & 127)) : mrow;
        int r1 = (EPI==1) ? ((((mrow+8)>>7)<<8) + 128 + ((mrow+8) & 127)) : (mrow+8);
        #pragma unroll
        for (int nf=0; nf<8; nf++){
            int c0 = n0 + wn*64 + nf*8 + 2*tig;
            float2 v0 = make_float2(acc[mf][nf][0], acc[mf][nf][1]);
            float2 v1 = make_float2(acc[mf][nf][2], acc[mf][nf][3]);
            if (EPI==2){
                const float2 r0v = *(const float2*)(resid + (size_t)r0*N + c0);
                const float2 r1v = *(const float2*)(resid + (size_t)r1*N + c0);
                v0.x += r0v.x; v0.y += r0v.y; v1.x += r1v.x; v1.y += r1v.y;
            } else if (EPI==1){
                float b0 = bias[c0], b1 = bias[c0+1];
                v0.x += b0; v0.y += b1; v1.x += b0; v1.y += b1;
            }
            *(float2*)(C + (size_t)r0*N + c0) = v0;
            *(float2*)(C + (size_t)r1*N + c0) = v1;
        }
    }
}

// ---------------- embedding assembly ----------------
__global__ void gather_embed(const int* __restrict__ ids, const float* __restrict__ table,
                             float* __restrict__ h)
{
    int b = blockIdx.x >> 7, s = blockIdx.x & 127;
    int id = ids[b*SP + s];
    const float4* src = (const float4*)(table + (size_t)id*D_LLM);
    float4* dst = (float4*)(h + (size_t)(b*SEQ + s)*D_LLM);
    #pragma unroll
    for (int it=0; it<4; it++) dst[threadIdx.x + it*256] = src[threadIdx.x + it*256];
}

__global__ void stage_tv(const float* __restrict__ text, const float* __restrict__ vision,
                         __half* __restrict__ tvh)
{
    int b = blockIdx.x >> 7, r = blockIdx.x & 127;
    const float* src = (r < 64) ? (text + (size_t)(b*64 + r)*768)
                                : (vision + (size_t)(b*64 + (r-64))*768);
    __half* dst = tvh + (size_t)blockIdx.x*768;
    #pragma unroll
    for (int it=0; it<3; it++){
        int i = threadIdx.x + it*256;
        dst[i] = __float2half_rn(src[i]);
    }
}

// ---------------- rmsnorm: MODE 0 = fp32 out, 1 = fp16 out ----------------
template<int MODE>
__global__ void rmsnorm_kernel(const float* __restrict__ in, const float* __restrict__ w,
                               float* __restrict__ outf, __half* __restrict__ outh)
{
    int row = blockIdx.x;
    const float* p = in + (size_t)row*D_LLM;
    float ss = 0.f;
    for (int d=threadIdx.x; d<D_LLM; d+=256){ float vv = p[d]; ss += vv*vv; }
    float tot = blockReduceSum(ss);
    float r = rsqrtf(tot*(1.0f/D_LLM) + EPSR);
    for (int d=threadIdx.x; d<D_LLM; d+=256){
        float v = p[d]*r*w[d];
        if (MODE==0) outf[(size_t)row*D_LLM + d] = v;
        else         outh[(size_t)row*D_LLM + d] = __float2half_rn(v);
    }
}

// ---------------- rope: angles computed once per (s,i), reused across heads ----------------
__global__ void rope_kernel(float* __restrict__ q, float* __restrict__ k)
{
    __shared__ float cs[64], ss[64];
    int m = blockIdx.x;
    int s = m & (SEQ-1);
    if (threadIdx.x < 64){
        int i = threadIdx.x;
        float invf = powf(10000.f, -(float)i * (1.f/64.f));
        float ang = (float)s * invf;
        float c, sn; sincosf(ang, &sn, &c);
        cs[i] = c; ss[i] = sn;
    }
    __syncthreads();
    float* qr = q + (size_t)m*D_LLM;
    float* kr = k + (size_t)m*D_LLM;
    for (int p = threadIdx.x; p < NH*64; p += 256){
        int hh = p >> 6, i = p & 63;
        float c = cs[i], sn = ss[i];
        int b0 = hh*HD + i;
        float x1 = qr[b0], x2 = qr[b0+64];
        qr[b0]    = x1*c - x2*sn;
        qr[b0+64] = x2*c + x1*sn;
        x1 = kr[b0]; x2 = kr[b0+64];
        kr[b0]    = x1*c - x2*sn;
        kr[b0+64] = x2*c + x1*sn;
    }
}

// ---------------- attention: scores (Q K^T * scale), per (b,h), 64x64 tiles ----------------
__global__ void __launch_bounds__(256)
attn_scores(const float* __restrict__ Q, const float* __restrict__ K, float* __restrict__ att)
{
    int bh = blockIdx.z;
    int b = bh >> 5, h = bh & 31;
    int i0 = blockIdx.y*64, j0 = blockIdx.x*64;
    if (j0 > i0) return;

    __shared__ float Qs[64][33], Ks[64][33];
    int tid = threadIdx.x;
    int ty = tid >> 4, tx = tid & 15;
    float acc[4][4];
    #pragma unroll
    for (int r=0;r<4;r++)
        #pragma unroll
        for (int c=0;c<4;c++) acc[r][c]=0.f;

    const float* Qb = Q + (size_t)(b*SEQ + i0)*D_LLM + h*HD;
    const float* Kb = K + (size_t)(b*SEQ + j0)*D_LLM + h*HD;

    for (int d0=0; d0<HD; d0+=32){
        #pragma unroll
        for (int it=0; it<2; it++){
            int qi = tid + it*256;
            int r = qi >> 3, c = (qi & 7) << 2;
            float4 va = *(const float4*)(Qb + (size_t)r*D_LLM + d0 + c);
            Qs[r][c]=va.x; Qs[r][c+1]=va.y; Qs[r][c+2]=va.z; Qs[r][c+3]=va.w;
            float4 vb = *(const float4*)(Kb + (size_t)r*D_LLM + d0 + c);
            Ks[r][c]=vb.x; Ks[r][c+1]=vb.y; Ks[r][c+2]=vb.z; Ks[r][c+3]=vb.w;
        }
        __syncthreads();
        #pragma unroll
        for (int kk=0;kk<32;kk++){
            float a[4], bb[4];
            #pragma unroll
            for (int r=0;r<4;r++) a[r]=Qs[ty*4+r][kk];
            #pragma unroll
            for (int c=0;c<4;c++) bb[c]=Ks[tx*4+c][kk];
            #pragma unroll
            for (int r=0;r<4;r++)
                #pragma unroll
                for (int c=0;c<4;c++) acc[r][c] += a[r]*bb[c];
        }
        __syncthreads();
    }
    const float scale = 0.08838834764831845f;
    float* out = att + ((size_t)bh*SEQ + i0)*SEQ + j0;
    #pragma unroll
    for (int r=0;r<4;r++)
        #pragma unroll
        for (int c=0;c<4;c++)
            out[(size_t)(ty*4+r)*SEQ + tx*4+c] = acc[r][c]*scale;
}

// ---------------- softmax with causal mask ----------------
__global__ void softmax_kernel(float* __restrict__ att)
{
    int row = blockIdx.x;
    int i = row & (SEQ-1);
    int j = threadIdx.x;
    float* p = att + (size_t)row*SEQ;
    float v = (j <= i) ? p[j] : -3.0e38f;
    float mx = blockReduceMax(v);
    float e = (j <= i) ? __expf(v - mx) : 0.f;
    float s = blockReduceSum(e);
    p[j] = e / s;
}

// ---------------- attention: O = P V (fp16 out: A-input of Wo GEMM) ----------------
__global__ void __launch_bounds__(256)
attn_av(const float* __restrict__ att, const float* __restrict__ V, __half* __restrict__ O)
{
    int bh = blockIdx.z;
    int b = bh >> 5, h = bh & 31;
    int i0 = blockIdx.y*64, d0 = blockIdx.x*64;

    __shared__ float Ps[64][33], Vs[32][65];
    int tid = threadIdx.x;
    int ty = tid >> 4, tx = tid & 15;
    float acc[4][4];
    #pragma unroll
    for (int r=0;r<4;r++)
        #pragma unroll
        for (int c=0;c<4;c++) acc[r][c]=0.f;

    const float* Pb = att + ((size_t)bh*SEQ + i0)*SEQ;
    const float* Vb = V + (size_t)(b*SEQ)*D_LLM + h*HD + d0;

    int jend = i0 + 64;
    for (int j0=0; j0<jend; j0+=32){
        #pragma unroll
        for (int it=0; it<2; it++){
            int qi = tid + it*256;
            int r = qi >> 3, c = (qi & 7) << 2;
            float4 va = *(const float4*)(Pb + (size_t)r*SEQ + j0 + c);
            Ps[r][c]=va.x; Ps[r][c+1]=va.y; Ps[r][c+2]=va.z; Ps[r][c+3]=va.w;
            int rv = qi >> 4, cv = (qi & 15) << 2;
            float4 vb = *(const float4*)(Vb + (size_t)(j0+rv)*D_LLM + cv);
            Vs[rv][cv]=vb.x; Vs[rv][cv+1]=vb.y; Vs[rv][cv+2]=vb.z; Vs[rv][cv+3]=vb.w;
        }
        __syncthreads();
        #pragma unroll
        for (int kk=0;kk<32;kk++){
            float a[4], bb[4];
            #pragma unroll
            for (int r=0;r<4;r++) a[r]=Ps[ty*4+r][kk];
            #pragma unroll
            for (int c=0;c<4;c++) bb[c]=Vs[kk][tx*4+c];
            #pragma unroll
            for (int r=0;r<4;r++)
                #pragma unroll
                for (int c=0;c<4;c++) acc[r][c] += a[r]*bb[c];
        }
        __syncthreads();
    }
    __half* out = O + (size_t)(b*SEQ + i0)*D_LLM + h*HD + d0;
    #pragma unroll
    for (int r=0;r<4;r++)
        #pragma unroll
        for (int c=0;c<4;c++)
            out[(size_t)(ty*4+r)*D_LLM + tx*4+c] = __float2half_rn(acc[r][c]);
}

// ---------------- silu(gate) * up -> fp16 (A-input of Wd GEMM) ----------------
__global__ void silu_mul(const float* __restrict__ g, const float* __restrict__ u,
                         __half* __restrict__ gh)
{
    size_t idx = (size_t)blockIdx.x*256 + threadIdx.x;
    float gv = g[idx];
    gh[idx] = __float2half_rn(gv / (1.f + __expf(-gv)) * u[idx]);
}

// ---------------- mean pool over sequence ----------------
__global__ void pool_kernel(const float* __restrict__ x, float* __restrict__ pool)
{
    int b = blockIdx.y;
    int d = blockIdx.x*256 + threadIdx.x;
    float acc = 0.f;
    const float* p = x + (size_t)(b*SEQ)*D_LLM + d;
    for (int s=0; s<SEQ; s++) acc += p[(size_t)s*D_LLM];
    pool[b*D_LLM + d] = acc * (1.f/SEQ);
}

// ---------------- head ----------------
__global__ void head1_kernel(const float* __restrict__ pool, const float* __restrict__ W1,
                             const float* __restrict__ b1, float* __restrict__ y1)
{
    __shared__ float sp[D_LLM];
    int b = blockIdx.y;
    for (int kk=threadIdx.x; kk<D_LLM; kk+=256) sp[kk]=pool[b*D_LLM+kk];
    __syncthreads();
    int n = blockIdx.x*256 + threadIdx.x;
    float acc = b1[n];
    for (int kk=0; kk<D_LLM; kk++) acc += sp[kk]*W1[(size_t)kk*768 + n];
    y1[b*768 + n] = acc;
}

__global__ void head2_kernel(const float* __restrict__ y1, const float* __restrict__ W2,
                             const float* __restrict__ b2, float* __restrict__ out)
{
    int b = blockIdx.x;
    float acc = 0.f;
    for (int kk=threadIdx.x; kk<768; kk+=256) acc += y1[b*768+kk]*W2[kk];
    float tot = blockReduceSum(acc);
    if (threadIdx.x==0) out[b] = tot + b2[0];
}

// ---------------- host orchestration ----------------
extern "C" void kernel_launch(void* const* d_in, const int* in_sizes, int n_in,
                              void* d_out, int out_size)
{
    const float* text   = (const float*)d_in[0];
    const float* vision = (const float*)d_in[1];
    const int*   ids    = (const int*)  d_in[2];
    const float* in_W   = (const float*)d_in[3];
    const float* in_b   = (const float*)d_in[4];
    const float* table  = (const float*)d_in[5];
    const float* Wq     = (const float*)d_in[6];
    const float* Wk     = (const float*)d_in[7];
    const float* Wv     = (const float*)d_in[8];
    const float* Wo     = (const float*)d_in[9];
    const float* ln1    = (const float*)d_in[10];
    const float* ln2    = (const float*)d_in[11];
    const float* Wg     = (const float*)d_in[12];
    const float* Wu     = (const float*)d_in[13];
    const float* Wd     = (const float*)d_in[14];
    const float* fnw    = (const float*)d_in[15];
    const float* o1W    = (const float*)d_in[16];
    const float* o1b    = (const float*)d_in[17];
    const float* o2W    = (const float*)d_in[18];
    const float* o2b    = (const float*)d_in[19];
    float* out = (float*)d_out;

    float *h,*x,*q,*k,*v,*att,*gate,*up,*pool,*y1;
    __half *xh,*oh,*gh,*tvh,*wh,*inWh;
    cudaGetSymbolAddress((void**)&h,    g_h);
    cudaGetSymbolAddress((void**)&x,    g_x);
    cudaGetSymbolAddress((void**)&xh,   g_xh);
    cudaGetSymbolAddress((void**)&q,    g_q);
    cudaGetSymbolAddress((void**)&k,    g_k);
    cudaGetSymbolAddress((void**)&v,    g_v);
    cudaGetSymbolAddress((void**)&oh,   g_oh);
    cudaGetSymbolAddress((void**)&att,  g_att);
    cudaGetSymbolAddress((void**)&gate, g_gate);
    cudaGetSymbolAddress((void**)&up,   g_up);
    cudaGetSymbolAddress((void**)&gh,   g_gh);
    cudaGetSymbolAddress((void**)&tvh,  g_tvh);
    cudaGetSymbolAddress((void**)&pool, g_pool);
    cudaGetSymbolAddress((void**)&y1,   g_y1);
    cudaGetSymbolAddress((void**)&wh,   g_wh);
    cudaGetSymbolAddress((void**)&inWh, g_inWh);

    cudaFuncSetAttribute(gemm_mma<0>, cudaFuncAttributeMaxDynamicSharedMemorySize, TC_SMEM);
    cudaFuncSetAttribute(gemm_mma<1>, cudaFuncAttributeMaxDynamicSharedMemorySize, TC_SMEM);
    cudaFuncSetAttribute(gemm_mma<2>, cudaFuncAttributeMaxDynamicSharedMemorySize, TC_SMEM);

    // one-time (per launch) fp16 conversion of all weights (k-pair interleaved, vectorized)
    auto cvt = [&](const float* src, __half* dst, int K, int N){
        int n = (K/2)*(N/4);
        cvt_w<<<(n + 255)/256, 256>>>(src, dst, N/4, K/2);
    };
    cvt(in_W, inWh, 768, D_LLM);
    for (int l=0; l<2; l++){
        __half* wl = wh + (size_t)l*LAYER_STRIDE;
        cvt(Wq + (size_t)l*WSZ_ATT, wl + L_WQ, D_LLM, D_LLM);
        cvt(Wk + (size_t)l*WSZ_ATT, wl + L_WK, D_LLM, D_LLM);
        cvt(Wv + (size_t)l*WSZ_ATT, wl + L_WV, D_LLM, D_LLM);
        cvt(Wo + (size_t)l*WSZ_ATT, wl + L_WO, D_LLM, D_LLM);
        cvt(Wg + (size_t)l*WSZ_FF,  wl + L_WG, D_LLM, D_FF);
        cvt(Wu + (size_t)l*WSZ_FF,  wl + L_WU, D_LLM, D_FF);
        cvt(Wd + (size_t)l*WSZ_FF,  wl + L_WD, D_FF,  D_LLM);
    }

    // --- embedding assembly
    gather_embed<<<NB*SP, 256>>>(ids, table, h);
    stage_tv<<<MTV, 256>>>(text, vision, tvh);
    gemm_mma<1><<<dim3(MTV/BM, D_LLM/BN), 256, TC_SMEM>>>(tvh, inWh, h, in_b, nullptr, MTV, D_LLM, 768);

    for (int l=0; l<2; l++){
        const __half* wq = wh + (size_t)l*LAYER_STRIDE + L_WQ;
        const __half* wk = wh + (size_t)l*LAYER_STRIDE + L_WK;
        const __half* wv = wh + (size_t)l*LAYER_STRIDE + L_WV;
        const __half* wo = wh + (size_t)l*LAYER_STRIDE + L_WO;
        const __half* wg = wh + (size_t)l*LAYER_STRIDE + L_WG;
        const __half* wu = wh + (size_t)l*LAYER_STRIDE + L_WU;
        const __half* wd = wh + (size_t)l*LAYER_STRIDE + L_WD;
        const float* l1 = ln1 + (size_t)l*D_LLM;
        const float* l2 = ln2 + (size_t)l*D_LLM;

        rmsnorm_kernel<1><<<MROWS, 256>>>(h, l1, nullptr, xh);
        gemm_mma<0><<<dim3(MROWS/BM, D_LLM/BN), 256, TC_SMEM>>>(xh, wq, q, nullptr, nullptr, MROWS, D_LLM, D_LLM);
        gemm_mma<0><<<dim3(MROWS/BM, D_LLM/BN), 256, TC_SMEM>>>(xh, wk, k, nullptr, nullptr, MROWS, D_LLM, D_LLM);
        gemm_mma<0><<<dim3(MROWS/BM, D_LLM/BN), 256, TC_SMEM>>>(xh, wv, v, nullptr, nullptr, MROWS, D_LLM, D_LLM);
        rope_kernel<<<MROWS, 256>>>(q, k);
        attn_scores<<<dim3(SEQ/64, SEQ/64, NB*NH), 256>>>(q, k, att);
        softmax_kernel<<<NB*NH*SEQ, 256>>>(att);
        attn_av<<<dim3(HD/64, SEQ/64, NB*NH), 256>>>(att, v, oh);
        gemm_mma<2><<<dim3(MROWS/BM, D_LLM/BN), 256, TC_SMEM>>>(oh, wo, h, nullptr, h, MROWS, D_LLM, D_LLM);

        rmsnorm_kernel<1><<<MROWS, 256>>>(h, l2, nullptr, xh);
        gemm_mma<0><<<dim3(MROWS/BM, D_FF/BN), 256, TC_SMEM>>>(xh, wg, gate, nullptr, nullptr, MROWS, D_FF, D_LLM);
        gemm_mma<0><<<dim3(MROWS/BM, D_FF/BN), 256, TC_SMEM>>>(xh, wu, up,   nullptr, nullptr, MROWS, D_FF, D_LLM);
        silu_mul<<<(MROWS*(size_t)D_FF)/256, 256>>>(gate, up, gh);
        gemm_mma<2><<<dim3(MROWS/BM, D_LLM/BN), 256, TC_SMEM>>>(gh, wd, h, nullptr, h, MROWS, D_LLM, D_FF);
    }

    rmsnorm_kernel<0><<<MROWS, 256>>>(h, fnw, x, nullptr);
    pool_kernel<<<dim3(D_LLM/256, NB), 256>>>(x, pool);
    head1_kernel<<<dim3(768/256, NB), 256>>>(pool, o1W, o1b, y1);
    head2_kernel<<<NB, 256>>>(y1, o2W, o2b, out);
}

// round 16
// speedup vs baseline: 1.0226x; 1.0226x over previous
#include <cuda_runtime.h>
#include <cuda_fp16.h>
#include <math.h>
#include <stdint.h>

// ---------------- problem constants ----------------
#define D_LLM 4096
#define D_FF  11008
#define NB    8
#define SEQ   256
#define SP    128
#define NH    32
#define HD    128
#define MROWS (NB*SEQ)          // 2048
#define MTV   (NB*128)          // 1024 text+vision rows
#define EPSR  1e-5f

// fp16 weight scratch layout (element offsets match fp32 source shapes)
#define WSZ_ATT  (D_LLM*D_LLM)
#define WSZ_FF   (D_LLM*D_FF)
#define L_WQ   ((size_t)0)
#define L_WK   ((size_t)1*WSZ_ATT)
#define L_WV   ((size_t)2*WSZ_ATT)
#define L_WO   ((size_t)3*WSZ_ATT)
#define L_WG   ((size_t)4*WSZ_ATT)
#define L_WU   ((size_t)4*WSZ_ATT + WSZ_FF)
#define L_WD   ((size_t)4*WSZ_ATT + 2*(size_t)WSZ_FF)
#define LAYER_STRIDE ((size_t)4*WSZ_ATT + 3*(size_t)WSZ_FF)

// ---------------- scratch (device globals; no allocation) ----------------
__device__ float  g_h   [MROWS*D_LLM];
__device__ float  g_x   [MROWS*D_LLM];
__device__ __half g_xh  [MROWS*D_LLM];
__device__ float  g_q   [MROWS*D_LLM];
__device__ float  g_k   [MROWS*D_LLM];
__device__ float  g_v   [MROWS*D_LLM];
__device__ __half g_oh  [MROWS*D_LLM];
__device__ float  g_att [NB*NH*SEQ*SEQ];
__device__ float  g_gate[MROWS*D_FF];
__device__ __half g_gh  [MROWS*D_FF];
__device__ __half g_tvh [MTV*768];
__device__ float  g_pool[NB*D_LLM];
__device__ float  g_y1  [NB*768];
__device__ __half g_wh  [2*LAYER_STRIDE];     // fp16, k-pair-interleaved weights
__device__ __half g_inWh[768*D_LLM];

// ---------------- helpers ----------------
__device__ __forceinline__ void cp_async16_s(uint32_t saddr, const void* gmem_src){
    asm volatile("cp.async.cg.shared.global [%0], [%1], 16;\n" :: "r"(saddr), "l"(gmem_src));
}
__device__ __forceinline__ void cp_commit(){
    asm volatile("cp.async.commit_group;\n" ::: "memory");
}
template<int N>
__device__ __forceinline__ void cp_wait(){
    asm volatile("cp.async.wait_group %0;\n" :: "n"(N) : "memory");
}

__device__ __forceinline__ void mma_f16(float* d, uint32_t a0, uint32_t a1, uint32_t a2, uint32_t a3,
                                        uint32_t b0, uint32_t b1){
    asm volatile(
        "mma.sync.aligned.m16n8k16.row.col.f32.f16.f16.f32 "
        "{%0,%1,%2,%3}, {%4,%5,%6,%7}, {%8,%9}, {%0,%1,%2,%3};"
        : "+f"(d[0]), "+f"(d[1]), "+f"(d[2]), "+f"(d[3])
        : "r"(a0), "r"(a1), "r"(a2), "r"(a3), "r"(b0), "r"(b1));
}

// ---------------- block reductions ----------------
__device__ __forceinline__ float blockReduceSum(float v){
    __shared__ float sh[33];
    int lane = threadIdx.x & 31, w = threadIdx.x >> 5;
    #pragma unroll
    for (int o=16;o>0;o>>=1) v += __shfl_down_sync(0xffffffffu, v, o);
    if (lane==0) sh[w]=v;
    __syncthreads();
    if (threadIdx.x==0){
        float s = 0.f;
        int nw = (blockDim.x+31)>>5;
        for (int i=0;i<nw;i++) s += sh[i];
        sh[32]=s;
    }
    __syncthreads();
    float r = sh[32];
    __syncthreads();
    return r;
}
__device__ __forceinline__ float blockReduceMax(float v){
    __shared__ float sh[33];
    int lane = threadIdx.x & 31, w = threadIdx.x >> 5;
    #pragma unroll
    for (int o=16;o>0;o>>=1) v = fmaxf(v, __shfl_down_sync(0xffffffffu, v, o));
    if (lane==0) sh[w]=v;
    __syncthreads();
    if (threadIdx.x==0){
        float s = -3.0e38f;
        int nw = (blockDim.x+31)>>5;
        for (int i=0;i<nw;i++) s = fmaxf(s, sh[i]);
        sh[32]=s;
    }
    __syncthreads();
    float r = sh[32];
    __syncthreads();
    return r;
}

// ---------------- weight fp32 -> fp16 with k-pair interleave (vectorized) ----------------
__global__ void cvt_w(const float* __restrict__ in, __half* __restrict__ out, int N4, int half_rows)
{
    int idx = blockIdx.x*256 + threadIdx.x;
    if (idx >= half_rows*N4) return;
    int k2 = idx / N4, n4 = idx - k2*N4;
    float4 v0 = ((const float4*)in)[(size_t)(2*k2  )*N4 + n4];
    float4 v1 = ((const float4*)in)[(size_t)(2*k2+1)*N4 + n4];
    __half2 h0 = __floats2half2_rn(v0.x, v1.x);
    __half2 h1 = __floats2half2_rn(v0.y, v1.y);
    __half2 h2 = __floats2half2_rn(v0.z, v1.z);
    __half2 h3 = __floats2half2_rn(v0.w, v1.w);
    uint4 pack;
    pack.x = *(uint32_t*)&h0; pack.y = *(uint32_t*)&h1;
    pack.z = *(uint32_t*)&h2; pack.w = *(uint32_t*)&h3;
    ((uint4*)out)[(size_t)k2*N4 + n4] = pack;
}

// ---------------- FP16 mma.sync GEMM, 256x128 tile, 8 warps (64x64 warp tile) ----------------
//   C[M,N](f32) = A[M,K](f16) @ B[K,N](f16, k-pair interleaved)
// EPI: 0 plain, 1 +bias & row-remap (in_proj), 2 += resid,
//      3 silu-fuse: Ch[r,c] = half( silu(gate[r,c]) * acc )
// Requires: M%256==0, N%128==0, K%32==0, K/32 >= 3.
#define TCS 3
#define BM 256
#define BN 128
#define CK 32
#define A_B32 20                 // b32 per A smem row (16 data + 4 pad)
#define A_STG (BM*A_B32)         // 5120 b32
#define B_B32 136                // b32 per B smem row (128 data + 8 pad)
#define B_STG ((CK/2)*B_B32)     // 2176 b32
#define TC_SMEM (TCS*(A_STG+B_STG)*4)   // 87552 B

template<int EPI>
__global__ void __launch_bounds__(256, 1)
gemm_mma(const __half* __restrict__ A, const __half* __restrict__ B,
         float* __restrict__ C, __half* __restrict__ Ch,
         const float* __restrict__ bias, const float* __restrict__ resid,
         int M, int N, int K)
{
    extern __shared__ uint32_t sm32[];
    const uint32_t sb = (uint32_t)__cvta_generic_to_shared(sm32);

    const int tid = threadIdx.x;
    const int wid = tid >> 5, lane = tid & 31;
    const int g   = lane >> 2, tig = lane & 3;
    const int wm  = wid >> 1;                // 0..3 (64 rows each)
    const int wn  = wid & 1;                 // 0..1 (64 cols each)
    const int m0  = blockIdx.x * BM;
    const int n0  = blockIdx.y * BN;
    const int KT  = K >> 5;
    const __half2* B2p = (const __half2*)B;

    float acc[4][8][4];                      // [mf][nf][reg]
    #pragma unroll
    for (int i=0;i<4;i++)
        #pragma unroll
        for (int j=0;j<8;j++)
            #pragma unroll
            for (int t=0;t<4;t++) acc[i][j][t]=0.f;

    auto load_chunk = [&](int st, int kc){
        const int k0 = kc << 5;              // in halves
        const uint32_t ab = sb + (uint32_t)(st*A_STG*4);
        const uint32_t bb = sb + (uint32_t)((TCS*A_STG + st*B_STG)*4);
        #pragma unroll
        for (int it=0; it<4; it++){                      // A: 256 rows x 4 x 16B (8 halves)
            int qi = tid + it*256;
            int r  = qi >> 2, c4 = qi & 3;
            cp_async16_s(ab + (uint32_t)(r*(A_B32*4) + c4*16),
                         A + (size_t)(m0+r)*K + k0 + c4*8);
        }
        #pragma unroll
        for (int it=0; it<2; it++){                      // B: 16 rows x 32 x 16B (4 half2)
            int qi = tid + it*256;
            int r2 = qi >> 5, cb = qi & 31;
            cp_async16_s(bb + (uint32_t)(r2*(B_B32*4) + cb*16),
                         B2p + (size_t)((k0>>1)+r2)*N + n0 + cb*4);
        }
    };

    auto compute = [&](int st){
        const uint32_t* As = sm32 + st*A_STG;
        const uint32_t* Bs = sm32 + TCS*A_STG + st*B_STG;
        #pragma unroll
        for (int ks2=0; ks2<CK/2; ks2+=8){   // two k-16 steps
            uint32_t bfr[8][2];
            #pragma unroll
            for (int nf=0; nf<8; nf++){
                int col = wn*64 + nf*8 + g;
                bfr[nf][0] = Bs[(ks2+tig  )*B_B32 + col];
                bfr[nf][1] = Bs[(ks2+tig+4)*B_B32 + col];
            }
            #pragma unroll
            for (int mf=0; mf<4; mf++){
                int row = wm*64 + mf*16;
                uint32_t a0 = As[(row+g  )*A_B32 + ks2 + tig  ];
                uint32_t a1 = As[(row+g+8)*A_B32 + ks2 + tig  ];
                uint32_t a2 = As[(row+g  )*A_B32 + ks2 + tig+4];
                uint32_t a3 = As[(row+g+8)*A_B32 + ks2 + tig+4];
                #pragma unroll
                for (int nf=0; nf<8; nf++)
                    mma_f16(acc[mf][nf], a0, a1, a2, a3, bfr[nf][0], bfr[nf][1]);
            }
        }
    };

    load_chunk(0, 0); cp_commit();
    load_chunk(1, 1); cp_commit();

    int st = 0;
    for (int kt=0; kt<KT; kt++){
        cp_wait<1>();
        __syncthreads();
        compute(st);
        int nc = kt + 2;
        if (nc < KT){
            int ns = st + 2; if (ns >= TCS) ns -= TCS;
            load_chunk(ns, nc);
        }
        cp_commit();
        st = (st+1 == TCS) ? 0 : st+1;
    }

    // epilogue
    #pragma unroll
    for (int mf=0; mf<4; mf++){
        int mrow = m0 + wm*64 + mf*16 + g;               // logical input row
        int r0 = (EPI==1) ? (((mrow>>7)<<8) + 128 + (mrow & 127)) : mrow;
        int r1 = (EPI==1) ? ((((mrow+8)>>7)<<8) + 128 + ((mrow+8) & 127)) : (mrow+8);
        #pragma unroll
        for (int nf=0; nf<8; nf++){
            int c0 = n0 + wn*64 + nf*8 + 2*tig;
            float2 v0 = make_float2(acc[mf][nf][0], acc[mf][nf][1]);
            float2 v1 = make_float2(acc[mf][nf][2], acc[mf][nf][3]);
            if (EPI==3){
                // silu(gate) * up, write fp16
                const float2 g0 = *(const float2*)(resid + (size_t)r0*N + c0);
                const float2 g1 = *(const float2*)(resid + (size_t)r1*N + c0);
                float s0 = g0.x / (1.f + __expf(-g0.x));
                float s1 = g0.y / (1.f + __expf(-g0.y));
                float s2 = g1.x / (1.f + __expf(-g1.x));
                float s3 = g1.y / (1.f + __expf(-g1.y));
                *(__half2*)(Ch + (size_t)r0*N + c0) = __floats2half2_rn(s0*v0.x, s1*v0.y);
                *(__half2*)(Ch + (size_t)r1*N + c0) = __floats2half2_rn(s2*v1.x, s3*v1.y);
                continue;
            }
            if (EPI==2){
                const float2 r0v = *(const float2*)(resid + (size_t)r0*N + c0);
                const float2 r1v = *(const float2*)(resid + (size_t)r1*N + c0);
                v0.x += r0v.x; v0.y += r0v.y; v1.x += r1v.x; v1.y += r1v.y;
            } else if (EPI==1){
                float b0 = bias[c0], b1 = bias[c0+1];
                v0.x += b0; v0.y += b1; v1.x += b0; v1.y += b1;
            }
            *(float2*)(C + (size_t)r0*N + c0) = v0;
            *(float2*)(C + (size_t)r1*N + c0) = v1;
        }
    }
}

// ---------------- embedding assembly ----------------
__global__ void gather_embed(const int* __restrict__ ids, const float* __restrict__ table,
                             float* __restrict__ h)
{
    int b = blockIdx.x >> 7, s = blockIdx.x & 127;
    int id = ids[b*SP + s];
    const float4* src = (const float4*)(table + (size_t)id*D_LLM);
    float4* dst = (float4*)(h + (size_t)(b*SEQ + s)*D_LLM);
    #pragma unroll
    for (int it=0; it<4; it++) dst[threadIdx.x + it*256] = src[threadIdx.x + it*256];
}

__global__ void stage_tv(const float* __restrict__ text, const float* __restrict__ vision,
                         __half* __restrict__ tvh)
{
    int b = blockIdx.x >> 7, r = blockIdx.x & 127;
    const float* src = (r < 64) ? (text + (size_t)(b*64 + r)*768)
                                : (vision + (size_t)(b*64 + (r-64))*768);
    __half* dst = tvh + (size_t)blockIdx.x*768;
    #pragma unroll
    for (int it=0; it<3; it++){
        int i = threadIdx.x + it*256;
        dst[i] = __float2half_rn(src[i]);
    }
}

// ---------------- rmsnorm: MODE 0 = fp32 out, 1 = fp16 out ----------------
template<int MODE>
__global__ void rmsnorm_kernel(const float* __restrict__ in, const float* __restrict__ w,
                               float* __restrict__ outf, __half* __restrict__ outh)
{
    int row = blockIdx.x;
    const float* p = in + (size_t)row*D_LLM;
    float ss = 0.f;
    for (int d=threadIdx.x; d<D_LLM; d+=256){ float vv = p[d]; ss += vv*vv; }
    float tot = blockReduceSum(ss);
    float r = rsqrtf(tot*(1.0f/D_LLM) + EPSR);
    for (int d=threadIdx.x; d<D_LLM; d+=256){
        float v = p[d]*r*w[d];
        if (MODE==0) outf[(size_t)row*D_LLM + d] = v;
        else         outh[(size_t)row*D_LLM + d] = __float2half_rn(v);
    }
}

// ---------------- rope: angles computed once per (s,i), reused across heads ----------------
__global__ void rope_kernel(float* __restrict__ q, float* __restrict__ k)
{
    __shared__ float cs[64], ss[64];
    int m = blockIdx.x;
    int s = m & (SEQ-1);
    if (threadIdx.x < 64){
        int i = threadIdx.x;
        float invf = powf(10000.f, -(float)i * (1.f/64.f));
        float ang = (float)s * invf;
        float c, sn; sincosf(ang, &sn, &c);
        cs[i] = c; ss[i] = sn;
    }
    __syncthreads();
    float* qr = q + (size_t)m*D_LLM;
    float* kr = k + (size_t)m*D_LLM;
    for (int p = threadIdx.x; p < NH*64; p += 256){
        int hh = p >> 6, i = p & 63;
        float c = cs[i], sn = ss[i];
        int b0 = hh*HD + i;
        float x1 = qr[b0], x2 = qr[b0+64];
        qr[b0]    = x1*c - x2*sn;
        qr[b0+64] = x2*c + x1*sn;
        x1 = kr[b0]; x2 = kr[b0+64];
        kr[b0]    = x1*c - x2*sn;
        kr[b0+64] = x2*c + x1*sn;
    }
}

// ---------------- attention: scores (Q K^T * scale), per (b,h), 64x64 tiles ----------------
__global__ void __launch_bounds__(256)
attn_scores(const float* __restrict__ Q, const float* __restrict__ K, float* __restrict__ att)
{
    int bh = blockIdx.z;
    int b = bh >> 5, h = bh & 31;
    int i0 = blockIdx.y*64, j0 = blockIdx.x*64;
    if (j0 > i0) return;

    __shared__ float Qs[64][33], Ks[64][33];
    int tid = threadIdx.x;
    int ty = tid >> 4, tx = tid & 15;
    float acc[4][4];
    #pragma unroll
    for (int r=0;r<4;r++)
        #pragma unroll
        for (int c=0;c<4;c++) acc[r][c]=0.f;

    const float* Qb = Q + (size_t)(b*SEQ + i0)*D_LLM + h*HD;
    const float* Kb = K + (size_t)(b*SEQ + j0)*D_LLM + h*HD;

    for (int d0=0; d0<HD; d0+=32){
        #pragma unroll
        for (int it=0; it<2; it++){
            int qi = tid + it*256;
            int r = qi >> 3, c = (qi & 7) << 2;
            float4 va = *(const float4*)(Qb + (size_t)r*D_LLM + d0 + c);
            Qs[r][c]=va.x; Qs[r][c+1]=va.y; Qs[r][c+2]=va.z; Qs[r][c+3]=va.w;
            float4 vb = *(const float4*)(Kb + (size_t)r*D_LLM + d0 + c);
            Ks[r][c]=vb.x; Ks[r][c+1]=vb.y; Ks[r][c+2]=vb.z; Ks[r][c+3]=vb.w;
        }
        __syncthreads();
        #pragma unroll
        for (int kk=0;kk<32;kk++){
            float a[4], bb[4];
            #pragma unroll
            for (int r=0;r<4;r++) a[r]=Qs[ty*4+r][kk];
            #pragma unroll
            for (int c=0;c<4;c++) bb[c]=Ks[tx*4+c][kk];
            #pragma unroll
            for (int r=0;r<4;r++)
                #pragma unroll
                for (int c=0;c<4;c++) acc[r][c] += a[r]*bb[c];
        }
        __syncthreads();
    }
    const float scale = 0.08838834764831845f;
    float* out = att + ((size_t)bh*SEQ + i0)*SEQ + j0;
    #pragma unroll
    for (int r=0;r<4;r++)
        #pragma unroll
        for (int c=0;c<4;c++)
            out[(size_t)(ty*4+r)*SEQ + tx*4+c] = acc[r][c]*scale;
}

// ---------------- softmax with causal mask ----------------
__global__ void softmax_kernel(float* __restrict__ att)
{
    int row = blockIdx.x;
    int i = row & (SEQ-1);
    int j = threadIdx.x;
    float* p = att + (size_t)row*SEQ;
    float v = (j <= i) ? p[j] : -3.0e38f;
    float mx = blockReduceMax(v);
    float e = (j <= i) ? __expf(v - mx) : 0.f;
    float s = blockReduceSum(e);
    p[j] = e / s;
}

// ---------------- attention: O = P V (fp16 out: A-input of Wo GEMM) ----------------
__global__ void __launch_bounds__(256)
attn_av(const float* __restrict__ att, const float* __restrict__ V, __half* __restrict__ O)
{
    int bh = blockIdx.z;
    int b = bh >> 5, h = bh & 31;
    int i0 = blockIdx.y*64, d0 = blockIdx.x*64;

    __shared__ float Ps[64][33], Vs[32][65];
    int tid = threadIdx.x;
    int ty = tid >> 4, tx = tid & 15;
    float acc[4][4];
    #pragma unroll
    for (int r=0;r<4;r++)
        #pragma unroll
        for (int c=0;c<4;c++) acc[r][c]=0.f;

    const float* Pb = att + ((size_t)bh*SEQ + i0)*SEQ;
    const float* Vb = V + (size_t)(b*SEQ)*D_LLM + h*HD + d0;

    int jend = i0 + 64;
    for (int j0=0; j0<jend; j0+=32){
        #pragma unroll
        for (int it=0; it<2; it++){
            int qi = tid + it*256;
            int r = qi >> 3, c = (qi & 7) << 2;
            float4 va = *(const float4*)(Pb + (size_t)r*SEQ + j0 + c);
            Ps[r][c]=va.x; Ps[r][c+1]=va.y; Ps[r][c+2]=va.z; Ps[r][c+3]=va.w;
            int rv = qi >> 4, cv = (qi & 15) << 2;
            float4 vb = *(const float4*)(Vb + (size_t)(j0+rv)*D_LLM + cv);
            Vs[rv][cv]=vb.x; Vs[rv][cv+1]=vb.y; Vs[rv][cv+2]=vb.z; Vs[rv][cv+3]=vb.w;
        }
        __syncthreads();
        #pragma unroll
        for (int kk=0;kk<32;kk++){
            float a[4], bb[4];
            #pragma unroll
            for (int r=0;r<4;r++) a[r]=Ps[ty*4+r][kk];
            #pragma unroll
            for (int c=0;c<4;c++) bb[c]=Vs[kk][tx*4+c];
            #pragma unroll
            for (int r=0;r<4;r++)
                #pragma unroll
                for (int c=0;c<4;c++) acc[r][c] += a[r]*bb[c];
        }
        __syncthreads();
    }
    __half* out = O + (size_t)(b*SEQ + i0)*D_LLM + h*HD + d0;
    #pragma unroll
    for (int r=0;r<4;r++)
        #pragma unroll
        for (int c=0;c<4;c++)
            out[(size_t)(ty*4+r)*D_LLM + tx*4+c] = __float2half_rn(acc[r][c]);
}

// ---------------- mean pool over sequence ----------------
__global__ void pool_kernel(const float* __restrict__ x, float* __restrict__ pool)
{
    int b = blockIdx.y;
    int d = blockIdx.x*256 + threadIdx.x;
    float acc = 0.f;
    const float* p = x + (size_t)(b*SEQ)*D_LLM + d;
    for (int s=0; s<SEQ; s++) acc += p[(size_t)s*D_LLM];
    pool[b*D_LLM + d] = acc * (1.f/SEQ);
}

// ---------------- head ----------------
__global__ void head1_kernel(const float* __restrict__ pool, const float* __restrict__ W1,
                             const float* __restrict__ b1, float* __restrict__ y1)
{
    __shared__ float sp[D_LLM];
    int b = blockIdx.y;
    for (int kk=threadIdx.x; kk<D_LLM; kk+=256) sp[kk]=pool[b*D_LLM+kk];
    __syncthreads();
    int n = blockIdx.x*256 + threadIdx.x;
    float acc = b1[n];
    for (int kk=0; kk<D_LLM; kk++) acc += sp[kk]*W1[(size_t)kk*768 + n];
    y1[b*768 + n] = acc;
}

__global__ void head2_kernel(const float* __restrict__ y1, const float* __restrict__ W2,
                             const float* __restrict__ b2, float* __restrict__ out)
{
    int b = blockIdx.x;
    float acc = 0.f;
    for (int kk=threadIdx.x; kk<768; kk+=256) acc += y1[b*768+kk]*W2[kk];
    float tot = blockReduceSum(acc);
    if (threadIdx.x==0) out[b] = tot + b2[0];
}

// ---------------- host orchestration ----------------
extern "C" void kernel_launch(void* const* d_in, const int* in_sizes, int n_in,
                              void* d_out, int out_size)
{
    const float* text   = (const float*)d_in[0];
    const float* vision = (const float*)d_in[1];
    const int*   ids    = (const int*)  d_in[2];
    const float* in_W   = (const float*)d_in[3];
    const float* in_b   = (const float*)d_in[4];
    const float* table  = (const float*)d_in[5];
    const float* Wq     = (const float*)d_in[6];
    const float* Wk     = (const float*)d_in[7];
    const float* Wv     = (const float*)d_in[8];
    const float* Wo     = (const float*)d_in[9];
    const float* ln1    = (const float*)d_in[10];
    const float* ln2    = (const float*)d_in[11];
    const float* Wg     = (const float*)d_in[12];
    const float* Wu     = (const float*)d_in[13];
    const float* Wd     = (const float*)d_in[14];
    const float* fnw    = (const float*)d_in[15];
    const float* o1W    = (const float*)d_in[16];
    const float* o1b    = (const float*)d_in[17];
    const float* o2W    = (const float*)d_in[18];
    const float* o2b    = (const float*)d_in[19];
    float* out = (float*)d_out;

    float *h,*x,*q,*k,*v,*att,*gate,*pool,*y1;
    __half *xh,*oh,*gh,*tvh,*wh,*inWh;
    cudaGetSymbolAddress((void**)&h,    g_h);
    cudaGetSymbolAddress((void**)&x,    g_x);
    cudaGetSymbolAddress((void**)&xh,   g_xh);
    cudaGetSymbolAddress((void**)&q,    g_q);
    cudaGetSymbolAddress((void**)&k,    g_k);
    cudaGetSymbolAddress((void**)&v,    g_v);
    cudaGetSymbolAddress((void**)&oh,   g_oh);
    cudaGetSymbolAddress((void**)&att,  g_att);
    cudaGetSymbolAddress((void**)&gate, g_gate);
    cudaGetSymbolAddress((void**)&gh,   g_gh);
    cudaGetSymbolAddress((void**)&tvh,  g_tvh);
    cudaGetSymbolAddress((void**)&pool, g_pool);
    cudaGetSymbolAddress((void**)&y1,   g_y1);
    cudaGetSymbolAddress((void**)&wh,   g_wh);
    cudaGetSymbolAddress((void**)&inWh, g_inWh);

    cudaFuncSetAttribute(gemm_mma<0>, cudaFuncAttributeMaxDynamicSharedMemorySize, TC_SMEM);
    cudaFuncSetAttribute(gemm_mma<1>, cudaFuncAttributeMaxDynamicSharedMemorySize, TC_SMEM);
    cudaFuncSetAttribute(gemm_mma<2>, cudaFuncAttributeMaxDynamicSharedMemorySize, TC_SMEM);
    cudaFuncSetAttribute(gemm_mma<3>, cudaFuncAttributeMaxDynamicSharedMemorySize, TC_SMEM);

    // one-time (per launch) fp16 conversion of all weights (k-pair interleaved, vectorized)
    auto cvt = [&](const float* src, __half* dst, int K, int N){
        int n = (K/2)*(N/4);
        cvt_w<<<(n + 255)/256, 256>>>(src, dst, N/4, K/2);
    };
    cvt(in_W, inWh, 768, D_LLM);
    for (int l=0; l<2; l++){
        __half* wl = wh + (size_t)l*LAYER_STRIDE;
        cvt(Wq + (size_t)l*WSZ_ATT, wl + L_WQ, D_LLM, D_LLM);
        cvt(Wk + (size_t)l*WSZ_ATT, wl + L_WK, D_LLM, D_LLM);
        cvt(Wv + (size_t)l*WSZ_ATT, wl + L_WV, D_LLM, D_LLM);
        cvt(Wo + (size_t)l*WSZ_ATT, wl + L_WO, D_LLM, D_LLM);
        cvt(Wg + (size_t)l*WSZ_FF,  wl + L_WG, D_LLM, D_FF);
        cvt(Wu + (size_t)l*WSZ_FF,  wl + L_WU, D_LLM, D_FF);
        cvt(Wd + (size_t)l*WSZ_FF,  wl + L_WD, D_FF,  D_LLM);
    }

    // --- embedding assembly
    gather_embed<<<NB*SP, 256>>>(ids, table, h);
    stage_tv<<<MTV, 256>>>(text, vision, tvh);
    gemm_mma<1><<<dim3(MTV/BM, D_LLM/BN), 256, TC_SMEM>>>(tvh, inWh, h, nullptr, in_b, nullptr, MTV, D_LLM, 768);

    for (int l=0; l<2; l++){
        const __half* wq = wh + (size_t)l*LAYER_STRIDE + L_WQ;
        const __half* wk = wh + (size_t)l*LAYER_STRIDE + L_WK;
        const __half* wv = wh + (size_t)l*LAYER_STRIDE + L_WV;
        const __half* wo = wh + (size_t)l*LAYER_STRIDE + L_WO;
        const __half* wg = wh + (size_t)l*LAYER_STRIDE + L_WG;
        const __half* wu = wh + (size_t)l*LAYER_STRIDE + L_WU;
        const __half* wd = wh + (size_t)l*LAYER_STRIDE + L_WD;
        const float* l1 = ln1 + (size_t)l*D_LLM;
        const float* l2 = ln2 + (size_t)l*D_LLM;

        rmsnorm_kernel<1><<<MROWS, 256>>>(h, l1, nullptr, xh);
        gemm_mma<0><<<dim3(MROWS/BM, D_LLM/BN), 256, TC_SMEM>>>(xh, wq, q, nullptr, nullptr, nullptr, MROWS, D_LLM, D_LLM);
        gemm_mma<0><<<dim3(MROWS/BM, D_LLM/BN), 256, TC_SMEM>>>(xh, wk, k, nullptr, nullptr, nullptr, MROWS, D_LLM, D_LLM);
        gemm_mma<0><<<dim3(MROWS/BM, D_LLM/BN), 256, TC_SMEM>>>(xh, wv, v, nullptr, nullptr, nullptr, MROWS, D_LLM, D_LLM);
        rope_kernel<<<MROWS, 256>>>(q, k);
        attn_scores<<<dim3(SEQ/64, SEQ/64, NB*NH), 256>>>(q, k, att);
        softmax_kernel<<<NB*NH*SEQ, 256>>>(att);
        attn_av<<<dim3(HD/64, SEQ/64, NB*NH), 256>>>(att, v, oh);
        gemm_mma<2><<<dim3(MROWS/BM, D_LLM/BN), 256, TC_SMEM>>>(oh, wo, h, nullptr, nullptr, h, MROWS, D_LLM, D_LLM);

        rmsnorm_kernel<1><<<MROWS, 256>>>(h, l2, nullptr, xh);
        gemm_mma<0><<<dim3(MROWS/BM, D_FF/BN), 256, TC_SMEM>>>(xh, wg, gate, nullptr, nullptr, nullptr, MROWS, D_FF, D_LLM);
        // up-GEMM with fused silu(gate)*up -> fp16
        gemm_mma<3><<<dim3(MROWS/BM, D_FF/BN), 256, TC_SMEM>>>(xh, wu, nullptr, gh, nullptr, gate, MROWS, D_FF, D_LLM);
        gemm_mma<2><<<dim3(MROWS/BM, D_LLM/BN), 256, TC_SMEM>>>(gh, wd, h, nullptr, nullptr, h, MROWS, D_LLM, D_FF);
    }

    rmsnorm_kernel<0><<<MROWS, 256>>>(h, fnw, x, nullptr);
    pool_kernel<<<dim3(D_LLM/256, NB), 256>>>(x, pool);
    head1_kernel<<<dim3(768/256, NB), 256>>>(pool, o1W, o1b, y1);
    head2_kernel<<<NB, 256>>>(y1, o2W, o2b, out);
}